// round 12
// baseline (speedup 1.0000x reference)
#include <cuda_runtime.h>

#define NN      8000
#define NFEATD  512
#define NHID    128
#define NCLS    64
#define CAP     128
#define NCHUNK  2000   // NN/4 uint4 chunks per adj row
#define NCSR    296    // persistent CSR worker blocks
#define ROWGRAB 8      // rows per steal

// ---- persistent scratch (no allocs allowed) ----
__device__ float g_h[NN * NHID];        // h = relu(xW0+b0) (== h0)
__device__ float g_li0[NN * NHID];
__device__ float g_li1[NN * NHID];
__device__ float g_yhat[NN * NCLS];
__device__ float g_w[NN * CAP];         // normalized edge weights (incl. 0.9/L1)
__device__ int   g_cols[NN * CAP];
__device__ int   g_nnz[NN];
__device__ int   g_ctr;                 // dynamic row counter for CSR workers

__global__ void k_reset() { g_ctr = 0; }

// ============================================================
// Merged kernel: blocks [0,125) = h-GEMM tiles,
// blocks [125,125+NCSR) = persistent CSR workers (dynamic stealing).
// ============================================================
#define SM_AS   (2 * 16 * 65)
#define SM_BS   (2 * 16 * 128)

__global__ void __launch_bounds__(256) k_main(
        const float* __restrict__ x,  const float* __restrict__ W0,
        const float* __restrict__ b0, const float* __restrict__ adj) {
    __shared__ __align__(16) float smem[SM_AS + SM_BS];

    if (blockIdx.x < 125) {
        // ---------- GEMM: 64x128 tile, BK=16, 256 thr, 4x8 micro ----------
        const int tid = threadIdx.x;
        const int tx = tid & 15, ty = tid >> 4;
        const int br = blockIdx.x * 64;
        float* As = smem;
        float* Bs = smem + SM_AS;

        const int ar = tid >> 2;
        const int ak = (tid & 3) * 4;
        const int bk = tid >> 5;
        const int bc = (tid & 31) * 4;

        float4 a_r, b_r0, b_r1;
        a_r  = *(const float4*)&x[(size_t)(br + ar) * NFEATD + ak];
        b_r0 = *(const float4*)&W0[(size_t)(bk)     * NHID + bc];
        b_r1 = *(const float4*)&W0[(size_t)(bk + 8) * NHID + bc];
        As[(0 + ak + 0) * 65 + ar] = a_r.x;
        As[(0 + ak + 1) * 65 + ar] = a_r.y;
        As[(0 + ak + 2) * 65 + ar] = a_r.z;
        As[(0 + ak + 3) * 65 + ar] = a_r.w;
        *(float4*)&Bs[(0 + bk)     * 128 + bc] = b_r0;
        *(float4*)&Bs[(0 + bk + 8) * 128 + bc] = b_r1;
        __syncthreads();

        float acc[4][8];
#pragma unroll
        for (int i = 0; i < 4; i++)
#pragma unroll
            for (int j = 0; j < 8; j++) acc[i][j] = 0.f;

        for (int kt = 0; kt < 32; kt++) {
            const int cur = (kt & 1) * 16, nxt = ((kt + 1) & 1) * 16;
            if (kt < 31) {
                const int k0 = (kt + 1) * 16;
                a_r  = *(const float4*)&x[(size_t)(br + ar) * NFEATD + k0 + ak];
                b_r0 = *(const float4*)&W0[(size_t)(k0 + bk)     * NHID + bc];
                b_r1 = *(const float4*)&W0[(size_t)(k0 + bk + 8) * NHID + bc];
            }
#pragma unroll
            for (int kk = 0; kk < 16; kk++) {
                float ra[4], rb[8];
#pragma unroll
                for (int i = 0; i < 4; i++) ra[i] = As[(cur + kk) * 65 + ty * 4 + i];
                *(float4*)&rb[0] = *(float4*)&Bs[(cur + kk) * 128 + tx * 8];
                *(float4*)&rb[4] = *(float4*)&Bs[(cur + kk) * 128 + tx * 8 + 4];
#pragma unroll
                for (int i = 0; i < 4; i++)
#pragma unroll
                    for (int j = 0; j < 8; j++) acc[i][j] += ra[i] * rb[j];
            }
            if (kt < 31) {
                As[(nxt + ak + 0) * 65 + ar] = a_r.x;
                As[(nxt + ak + 1) * 65 + ar] = a_r.y;
                As[(nxt + ak + 2) * 65 + ar] = a_r.z;
                As[(nxt + ak + 3) * 65 + ar] = a_r.w;
                *(float4*)&Bs[(nxt + bk)     * 128 + bc] = b_r0;
                *(float4*)&Bs[(nxt + bk + 8) * 128 + bc] = b_r1;
            }
            __syncthreads();
        }

        const float4 bv0 = *(const float4*)&b0[tx * 8];
        const float4 bv1 = *(const float4*)&b0[tx * 8 + 4];
#pragma unroll
        for (int i = 0; i < 4; i++) {
            const int r = br + ty * 4 + i;
            float4 o0, o1;
            o0.x = fmaxf(acc[i][0] + bv0.x, 0.f);
            o0.y = fmaxf(acc[i][1] + bv0.y, 0.f);
            o0.z = fmaxf(acc[i][2] + bv0.z, 0.f);
            o0.w = fmaxf(acc[i][3] + bv0.w, 0.f);
            o1.x = fmaxf(acc[i][4] + bv1.x, 0.f);
            o1.y = fmaxf(acc[i][5] + bv1.y, 0.f);
            o1.z = fmaxf(acc[i][6] + bv1.z, 0.f);
            o1.w = fmaxf(acc[i][7] + bv1.w, 0.f);
            *(float4*)&g_h[(size_t)r * NHID + tx * 8]       = o0;
            *(float4*)&g_h[(size_t)r * NHID + tx * 8 + 4]   = o1;
            *(float4*)&g_li0[(size_t)r * NHID + tx * 8]     = o0;
            *(float4*)&g_li0[(size_t)r * NHID + tx * 8 + 4] = o1;
        }
    } else {
        // ---------- persistent CSR worker: dynamic 8-row chunks ----------
        const int t = threadIdx.x;
        __shared__ int scnt;   // per-row nnz counter
        __shared__ int srow;   // chunk start
        for (;;) {
            if (t == 0) srow = atomicAdd(&g_ctr, ROWGRAB);
            __syncthreads();
            const int row0 = srow;
            if (row0 >= NN) break;
            const int rend = (row0 + ROWGRAB < NN) ? row0 + ROWGRAB : NN;
            for (int i = row0; i < rend; i++) {
                if (t == 0) scnt = 0;
                __syncthreads();
                const uint4* row4 = (const uint4*)(adj + (size_t)i * NN);
                uint4 c[8];
#pragma unroll
                for (int k = 0; k < 7; k++) c[k] = row4[t + 256 * k];
                {
                    const int idx7 = t + 256 * 7;
                    if (idx7 < NCHUNK) c[7] = row4[idx7];
                    else               c[7] = make_uint4(0u, 0u, 0u, 0u);
                }
                unsigned allor = 0u;
#pragma unroll
                for (int k = 0; k < 8; k++)
                    allor |= (c[k].x | c[k].y) | (c[k].z | c[k].w);
                if (allor) {
#pragma unroll
                    for (int k = 0; k < 8; k++) {
                        const unsigned oc = (c[k].x | c[k].y) | (c[k].z | c[k].w);
                        if (oc) {
                            const int base = (t + 256 * k) * 4;
                            if (c[k].x) { int p = atomicAdd(&scnt, 1); if (p < CAP) g_cols[i * CAP + p] = base + 0; }
                            if (c[k].y) { int p = atomicAdd(&scnt, 1); if (p < CAP) g_cols[i * CAP + p] = base + 1; }
                            if (c[k].z) { int p = atomicAdd(&scnt, 1); if (p < CAP) g_cols[i * CAP + p] = base + 2; }
                            if (c[k].w) { int p = atomicAdd(&scnt, 1); if (p < CAP) g_cols[i * CAP + p] = base + 3; }
                        }
                    }
                }
                __syncthreads();
                if (t == 0) g_nnz[i] = (scnt < CAP) ? scnt : CAP;
                // t0 reads scnt then rewrites it next iter (program order);
                // other threads wait at the post-reset __syncthreads().
            }
        }
    }
}

// ============================================================
// Fused: Pseudo = h@W1+b1, label injection (count-based, dup-safe),
// softmax -> g_yhat, Pseudo -> output. 4 rows per block, 64 threads.
// ============================================================
__global__ void __launch_bounds__(64) k_pseudo_sm(
        const float* __restrict__ W1, const float* __restrict__ b1,
        const int* __restrict__ idx, const float* __restrict__ y,
        float* __restrict__ out_pseudo) {
    const int base = blockIdx.x * 4, t = threadIdx.x;
    __shared__ __align__(16) float sh[4 * NHID];
    __shared__ float sred[4 * NCLS];
    __shared__ float smx[4], ssum[4];
    __shared__ int scnt[4];
    if (t < 4) scnt[t] = 0;
    const float4* hp = (const float4*)&g_h[(size_t)base * NHID];
    ((float4*)sh)[t]      = hp[t];
    ((float4*)sh)[t + 64] = hp[t + 64];
    __syncthreads();

    const float b = b1[t];
    float a0 = b, a1 = b, a2 = b, a3 = b;
#pragma unroll 8
    for (int k = 0; k < NHID; k++) {
        const float w = W1[k * NCLS + t];
        a0 += sh[k] * w;
        a1 += sh[NHID + k] * w;
        a2 += sh[2 * NHID + k] * w;
        a3 += sh[3 * NHID + k] * w;
    }
    for (int e = t; e < 500; e += 64) {
        const int v = idx[e] - base;
        if ((unsigned)v < 4u) atomicAdd(&scnt[v], 1);
    }
    __syncthreads();
    if (scnt[0]) a0 += 0.1f * scnt[0] * y[(size_t)(base + 0) * NCLS + t];
    if (scnt[1]) a1 += 0.1f * scnt[1] * y[(size_t)(base + 1) * NCLS + t];
    if (scnt[2]) a2 += 0.1f * scnt[2] * y[(size_t)(base + 2) * NCLS + t];
    if (scnt[3]) a3 += 0.1f * scnt[3] * y[(size_t)(base + 3) * NCLS + t];

    out_pseudo[(size_t)(base + 0) * NCLS + t] = a0;
    out_pseudo[(size_t)(base + 1) * NCLS + t] = a1;
    out_pseudo[(size_t)(base + 2) * NCLS + t] = a2;
    out_pseudo[(size_t)(base + 3) * NCLS + t] = a3;
    sred[t] = a0; sred[NCLS + t] = a1; sred[2 * NCLS + t] = a2; sred[3 * NCLS + t] = a3;
    __syncthreads();

    const int warp = t >> 5, lane = t & 31;
#pragma unroll
    for (int rr = 0; rr < 2; rr++) {
        const int r = warp * 2 + rr;
        float m = fmaxf(sred[r * NCLS + lane], sred[r * NCLS + lane + 32]);
#pragma unroll
        for (int o = 16; o; o >>= 1) m = fmaxf(m, __shfl_xor_sync(~0u, m, o));
        float s = expf(sred[r * NCLS + lane] - m) + expf(sred[r * NCLS + lane + 32] - m);
#pragma unroll
        for (int o = 16; o; o >>= 1) s += __shfl_xor_sync(~0u, s, o);
        if (lane == 0) { smx[r] = m; ssum[r] = 1.f / s; }
    }
    __syncthreads();
    g_yhat[(size_t)(base + 0) * NCLS + t] = expf(a0 - smx[0]) * ssum[0];
    g_yhat[(size_t)(base + 1) * NCLS + t] = expf(a1 - smx[1]) * ssum[1];
    g_yhat[(size_t)(base + 2) * NCLS + t] = expf(a2 - smx[2]) * ssum[2];
    g_yhat[(size_t)(base + 3) * NCLS + t] = expf(a3 - smx[3]) * ssum[3];
}

// ============================================================
// Layer 1, fully fused (warp per row, 4 rows / 128-thr block):
//  A: w_e = dot(yhat_i,yhat_j), normalize (0.9/L1), keep in smem + g_w
//  B: li1 = L2norm( sum w_e*li0[j] + 0.1*h0 )   (unroll-4 gather)
// ============================================================
__global__ void __launch_bounds__(128) k_prop1() {
    const int w    = threadIdx.x >> 5;
    const int lane = threadIdx.x & 31;
    const int i    = blockIdx.x * 4 + w;
    __shared__ int   sj[4][CAP];
    __shared__ float sw[4][CAP];

    const int nnz = g_nnz[i];
    int* jrow = sj[w];
    float* wrow = sw[w];
    for (int e = lane; e < nnz; e += 32) jrow[e] = g_cols[i * CAP + e];
    __syncwarp();

    // --- phase A: edge dots ---
    const float2 ya = ((const float2*)(g_yhat + (size_t)i * NCLS))[lane];
    int e = 0;
    for (; e + 2 <= nnz; e += 2) {
        const float2 v0 = ((const float2*)(g_yhat + (size_t)jrow[e]     * NCLS))[lane];
        const float2 v1 = ((const float2*)(g_yhat + (size_t)jrow[e + 1] * NCLS))[lane];
        float p0 = ya.x * v0.x + ya.y * v0.y;
        float p1 = ya.x * v1.x + ya.y * v1.y;
#pragma unroll
        for (int o = 16; o; o >>= 1) {
            p0 += __shfl_xor_sync(~0u, p0, o);
            p1 += __shfl_xor_sync(~0u, p1, o);
        }
        if (lane == 0) { wrow[e] = p0; wrow[e + 1] = p1; }
    }
    if (e < nnz) {
        const float2 v0 = ((const float2*)(g_yhat + (size_t)jrow[e] * NCLS))[lane];
        float p0 = ya.x * v0.x + ya.y * v0.y;
#pragma unroll
        for (int o = 16; o; o >>= 1) p0 += __shfl_xor_sync(~0u, p0, o);
        if (lane == 0) wrow[e] = p0;
    }
    __syncwarp();
    float s = 0.f;
    for (int q = lane; q < nnz; q += 32) s += wrow[q];
#pragma unroll
    for (int o = 16; o; o >>= 1) s += __shfl_xor_sync(~0u, s, o);
    const float scale = 0.9f / fmaxf(s, 1e-12f);
    for (int q = lane; q < nnz; q += 32) {
        const float v = wrow[q] * scale;
        wrow[q] = v;
        g_w[i * CAP + q] = v;        // reused by layer 2
    }
    __syncwarp();

    // --- phase B: gather li0 -> li1 ---
    const float4 h4 = ((const float4*)(g_h + (size_t)i * NHID))[lane];
    float4 A0 = make_float4(0.1f * h4.x, 0.1f * h4.y, 0.1f * h4.z, 0.1f * h4.w);
    float4 A1 = make_float4(0.f, 0.f, 0.f, 0.f);
    float4 A2 = make_float4(0.f, 0.f, 0.f, 0.f);
    float4 A3 = make_float4(0.f, 0.f, 0.f, 0.f);
    e = 0;
    for (; e + 4 <= nnz; e += 4) {
        const float w0 = wrow[e],     w1 = wrow[e + 1];
        const float w2 = wrow[e + 2], w3 = wrow[e + 3];
        const float4 v0 = ((const float4*)(g_li0 + (size_t)jrow[e]     * NHID))[lane];
        const float4 v1 = ((const float4*)(g_li0 + (size_t)jrow[e + 1] * NHID))[lane];
        const float4 v2 = ((const float4*)(g_li0 + (size_t)jrow[e + 2] * NHID))[lane];
        const float4 v3 = ((const float4*)(g_li0 + (size_t)jrow[e + 3] * NHID))[lane];
        A0.x += w0 * v0.x; A0.y += w0 * v0.y; A0.z += w0 * v0.z; A0.w += w0 * v0.w;
        A1.x += w1 * v1.x; A1.y += w1 * v1.y; A1.z += w1 * v1.z; A1.w += w1 * v1.w;
        A2.x += w2 * v2.x; A2.y += w2 * v2.y; A2.z += w2 * v2.z; A2.w += w2 * v2.w;
        A3.x += w3 * v3.x; A3.y += w3 * v3.y; A3.z += w3 * v3.z; A3.w += w3 * v3.w;
    }
    for (; e < nnz; e++) {
        const float w0 = wrow[e];
        const float4 v0 = ((const float4*)(g_li0 + (size_t)jrow[e] * NHID))[lane];
        A0.x += w0 * v0.x; A0.y += w0 * v0.y; A0.z += w0 * v0.z; A0.w += w0 * v0.w;
    }
    float4 acc = make_float4(A0.x + A1.x + A2.x + A3.x, A0.y + A1.y + A2.y + A3.y,
                             A0.z + A1.z + A2.z + A3.z, A0.w + A1.w + A2.w + A3.w);
    float sq = acc.x * acc.x + acc.y * acc.y + acc.z * acc.z + acc.w * acc.w;
#pragma unroll
    for (int o = 16; o; o >>= 1) sq += __shfl_xor_sync(~0u, sq, o);
    const float inv = 1.f / fmaxf(sqrtf(sq), 1e-12f);
    acc.x *= inv; acc.y *= inv; acc.z *= inv; acc.w *= inv;
    ((float4*)(g_li1 + (size_t)i * NHID))[lane] = acc;
}

// ============================================================
// Layer 2 gather (weights precomputed): li1 -> li0, unroll-4
// ============================================================
__global__ void __launch_bounds__(128) k_gather2() {
    const int i    = blockIdx.x * 4 + (threadIdx.x >> 5);
    const int lane = threadIdx.x & 31;
    const int nnz  = g_nnz[i];
    const int*   __restrict__ cols = &g_cols[i * CAP];
    const float* __restrict__ wts  = &g_w[i * CAP];

    const float4 h4 = ((const float4*)(g_h + (size_t)i * NHID))[lane];
    float4 A0 = make_float4(0.1f * h4.x, 0.1f * h4.y, 0.1f * h4.z, 0.1f * h4.w);
    float4 A1 = make_float4(0.f, 0.f, 0.f, 0.f);
    float4 A2 = make_float4(0.f, 0.f, 0.f, 0.f);
    float4 A3 = make_float4(0.f, 0.f, 0.f, 0.f);
    int e = 0;
    for (; e + 4 <= nnz; e += 4) {
        const int j0 = cols[e], j1 = cols[e + 1], j2 = cols[e + 2], j3 = cols[e + 3];
        const float w0 = wts[e], w1 = wts[e + 1], w2 = wts[e + 2], w3 = wts[e + 3];
        const float4 v0 = ((const float4*)(g_li1 + (size_t)j0 * NHID))[lane];
        const float4 v1 = ((const float4*)(g_li1 + (size_t)j1 * NHID))[lane];
        const float4 v2 = ((const float4*)(g_li1 + (size_t)j2 * NHID))[lane];
        const float4 v3 = ((const float4*)(g_li1 + (size_t)j3 * NHID))[lane];
        A0.x += w0 * v0.x; A0.y += w0 * v0.y; A0.z += w0 * v0.z; A0.w += w0 * v0.w;
        A1.x += w1 * v1.x; A1.y += w1 * v1.y; A1.z += w1 * v1.z; A1.w += w1 * v1.w;
        A2.x += w2 * v2.x; A2.y += w2 * v2.y; A2.z += w2 * v2.z; A2.w += w2 * v2.w;
        A3.x += w3 * v3.x; A3.y += w3 * v3.y; A3.z += w3 * v3.z; A3.w += w3 * v3.w;
    }
    for (; e < nnz; e++) {
        const float w0 = wts[e];
        const float4 v0 = ((const float4*)(g_li1 + (size_t)cols[e] * NHID))[lane];
        A0.x += w0 * v0.x; A0.y += w0 * v0.y; A0.z += w0 * v0.z; A0.w += w0 * v0.w;
    }
    float4 acc = make_float4(A0.x + A1.x + A2.x + A3.x, A0.y + A1.y + A2.y + A3.y,
                             A0.z + A1.z + A2.z + A3.z, A0.w + A1.w + A2.w + A3.w);
    float sq = acc.x * acc.x + acc.y * acc.y + acc.z * acc.z + acc.w * acc.w;
#pragma unroll
    for (int o = 16; o; o >>= 1) sq += __shfl_xor_sync(~0u, sq, o);
    const float inv = 1.f / fmaxf(sqrtf(sq), 1e-12f);
    acc.x *= inv; acc.y *= inv; acc.z *= inv; acc.w *= inv;
    ((float4*)(g_li0 + (size_t)i * NHID))[lane] = acc;
}

// ============================================================
// out = log_softmax(li @ W2 + b2), 4 rows per block, 64 threads
// ============================================================
__global__ void __launch_bounds__(64) k_out(
        const float* __restrict__ W2, const float* __restrict__ b2,
        float* __restrict__ out) {
    const int base = blockIdx.x * 4, t = threadIdx.x;
    __shared__ __align__(16) float sh[4 * NHID];
    __shared__ float sred[4 * NCLS];
    __shared__ float smx[4], ssum[4];
    const float4* lp = (const float4*)&g_li0[(size_t)base * NHID];
    ((float4*)sh)[t]      = lp[t];
    ((float4*)sh)[t + 64] = lp[t + 64];
    __syncthreads();

    const float b = b2[t];
    float a0 = b, a1 = b, a2 = b, a3 = b;
#pragma unroll 8
    for (int k = 0; k < NHID; k++) {
        const float w = W2[k * NCLS + t];
        a0 += sh[k] * w;
        a1 += sh[NHID + k] * w;
        a2 += sh[2 * NHID + k] * w;
        a3 += sh[3 * NHID + k] * w;
    }
    sred[t] = a0; sred[NCLS + t] = a1; sred[2 * NCLS + t] = a2; sred[3 * NCLS + t] = a3;
    __syncthreads();

    const int warp = t >> 5, lane = t & 31;
#pragma unroll
    for (int rr = 0; rr < 2; rr++) {
        const int r = warp * 2 + rr;
        float m = fmaxf(sred[r * NCLS + lane], sred[r * NCLS + lane + 32]);
#pragma unroll
        for (int o = 16; o; o >>= 1) m = fmaxf(m, __shfl_xor_sync(~0u, m, o));
        float s = expf(sred[r * NCLS + lane] - m) + expf(sred[r * NCLS + lane + 32] - m);
#pragma unroll
        for (int o = 16; o; o >>= 1) s += __shfl_xor_sync(~0u, s, o);
        if (lane == 0) { smx[r] = m; ssum[r] = logf(s); }
    }
    __syncthreads();
    out[(size_t)(base + 0) * NCLS + t] = a0 - smx[0] - ssum[0];
    out[(size_t)(base + 1) * NCLS + t] = a1 - smx[1] - ssum[1];
    out[(size_t)(base + 2) * NCLS + t] = a2 - smx[2] - ssum[2];
    out[(size_t)(base + 3) * NCLS + t] = a3 - smx[3] - ssum[3];
}

// ============================================================
extern "C" void kernel_launch(void* const* d_in, const int* in_sizes, int n_in,
                              void* d_out, int out_size) {
    const float* x   = (const float*)d_in[0];
    const float* adj = (const float*)d_in[1];
    const float* y   = (const float*)d_in[2];
    const int*   idx = (const int*)  d_in[3];
    const float* W0  = (const float*)d_in[4];
    const float* b0  = (const float*)d_in[5];
    const float* W1  = (const float*)d_in[6];
    const float* b1  = (const float*)d_in[7];
    const float* W2  = (const float*)d_in[8];
    const float* b2  = (const float*)d_in[9];
    (void)in_sizes; (void)n_in; (void)out_size;

    float* out_logsm  = (float*)d_out;                       // [8000,64]
    float* out_pseudo = (float*)d_out + (size_t)NN * NCLS;   // [8000,64]

    k_reset<<<1, 1>>>();                             // counter (graph-replay safe)
    k_main<<<125 + NCSR, 256>>>(x, W0, b0, adj);     // GEMM + persistent CSR
    k_pseudo_sm<<<NN / 4, 64>>>(W1, b1, idx, y, out_pseudo);
    k_prop1<<<NN / 4, 128>>>();                      // weights + li0 -> li1
    k_gather2<<<NN / 4, 128>>>();                    // li1 -> li0
    k_out<<<NN / 4, 64>>>(W2, b2, out_logsm);        // log_softmax output
}